// round 2
// baseline (speedup 1.0000x reference)
#include <cuda_runtime.h>
#include <math.h>

#define CC 128
#define HS 64
#define LL 4096
#define ND 2048   // CC*16
#define NB 2

// ---------------- device scratch (module-scope, no runtime alloc) -------------
__device__ float g_fds[NB * CC * LL];
__device__ float g_bds[NB * CC * LL];
__device__ float g_S[NB * LL];
__device__ float g_inorm[NB * LL];
__device__ float g_mm[LL];
__device__ float g_bufA[(size_t)NB * LL * LL];   // G -> z1 -> Emm
__device__ float g_bufB[(size_t)NB * LL * LL];   // yscore -> yfused
__device__ float g_pmax[NB * 16 * LL];
__device__ float g_psum[NB * 16 * LL];
__device__ float g_cmax[NB * LL];
__device__ float g_rinv[NB * LL];
__device__ float g_wmat[(size_t)NB * LL * ND];
__device__ float g_v[(size_t)NB * LL * ND];

// ---------------- small kernels ----------------------------------------------
__global__ void k_downsample(const float* __restrict__ f, const float* __restrict__ b) {
    int idx = blockIdx.x * 256 + threadIdx.x;           // NB*CC*64*64
    int j = idx & 63, i = (idx >> 6) & 63;
    int c = (idx >> 12) & 127, bb = idx >> 19;
    size_t src = ((size_t)(bb * CC + c) * 128 + 2 * i) * 128 + 2 * j;
    g_fds[idx] = f[src];
    g_bds[idx] = b[src];
}

__global__ void k_stats() {                              // S[b][l] = sum_c bds^2
    int idx = blockIdx.x * 256 + threadIdx.x;            // NB*LL
    int bb = idx >> 12; int l = idx & 4095;
    float acc = 0.f;
    for (int c = 0; c < CC; c++) {
        float v = g_bds[((size_t)bb * CC + c) * LL + l];
        acc = fmaf(v, v, acc);
    }
    g_S[idx] = acc;
}

__global__ void k_normmm(const float* __restrict__ mask) {
    int idx = blockIdx.x * 256 + threadIdx.x;            // NB*LL
    int bb = idx >> 12; int l = idx & 4095;
    int i = l >> 6, j = l & 63;
    float acc = 0.1152f;                                 // 1152 * 1e-4
    float msum = 0.f;
    for (int du = -1; du <= 1; du++)
        for (int dv = -1; dv <= 1; dv++) {
            int ii = i + du, jj = j + dv;
            if (ii >= 0 && ii < 64 && jj >= 0 && jj < 64) {
                acc += g_S[bb * LL + ii * 64 + jj];
                if (bb == 0) msum += mask[(2 * ii) * 128 + 2 * jj];
            }
        }
    g_inorm[idx] = rsqrtf(acc);
    if (bb == 0) g_mm[l] = (msum == 0.f) ? 1.f : 0.f;
}

// ---------------- packed f32x2 SGEMM: C[m][n] = sum_k A[k][m]*B[k][n] ---------
#define BM 128
#define BN 128
#define BKK 16

__device__ __forceinline__ unsigned long long dup2(float x) {
    unsigned long long r;
    asm("mov.b64 %0, {%1, %2};" : "=l"(r) : "f"(x), "f"(x));
    return r;
}
__device__ __forceinline__ void ffma2(unsigned long long& d, unsigned long long a, unsigned long long b) {
    asm("fma.rn.f32x2 %0, %1, %2, %0;" : "+l"(d) : "l"(a), "l"(b));
}

// mode 0: Gram  A=g_bds B=g_fds C=g_bufA   (M=N=4096,K=128)
// mode 1: Attn  A=g_bufA(E) B=g_wmat C=g_v (M=4096,N=2048,K=4096)
__global__ __launch_bounds__(256, 2)
void gemm_tn(int mode, int M, int N, int K, size_t sA, size_t sB, size_t sC) {
    const float* A; const float* Bm; float* Cm;
    if (mode == 0) { A = g_bds; Bm = g_fds; Cm = g_bufA; }
    else           { A = g_bufA; Bm = g_wmat; Cm = g_v; }
    __shared__ float As[BKK][BM];
    __shared__ float Bs[BKK][BN];
    const int tid = threadIdx.x;
    const int m0 = blockIdx.y * BM, n0 = blockIdx.x * BN;
    const int z = blockIdx.z;
    A += (size_t)z * sA; Bm += (size_t)z * sB; Cm += (size_t)z * sC;

    int lk[2], lm4[2];
#pragma unroll
    for (int r = 0; r < 2; r++) {
        int idx = tid + r * 256;
        lk[r] = idx >> 5;
        lm4[r] = (idx & 31) << 2;
    }

    unsigned long long acc[4][8];
#pragma unroll
    for (int a = 0; a < 4; a++)
#pragma unroll
        for (int b = 0; b < 8; b++) acc[a][b] = 0ull;

    const int ty = tid >> 4, tx = tid & 15;

    for (int k0 = 0; k0 < K; k0 += BKK) {
#pragma unroll
        for (int r = 0; r < 2; r++) {
            *(float4*)&As[lk[r]][lm4[r]] = *(const float4*)&A[(size_t)(k0 + lk[r]) * M + m0 + lm4[r]];
            *(float4*)&Bs[lk[r]][lm4[r]] = *(const float4*)&Bm[(size_t)(k0 + lk[r]) * N + n0 + lm4[r]];
        }
        __syncthreads();
#pragma unroll
        for (int kk = 0; kk < BKK; kk++) {
            const ulonglong2* A2 = (const ulonglong2*)&As[kk][0];
            ulonglong2 av0 = A2[ty];
            ulonglong2 av1 = A2[16 + ty];
            unsigned long long ap[4] = {av0.x, av0.y, av1.x, av1.y};
            const float4* B4 = (const float4*)&Bs[kk][0];
            float4 bv0 = B4[tx], bv1 = B4[16 + tx];
            unsigned long long bd[8] = {dup2(bv0.x), dup2(bv0.y), dup2(bv0.z), dup2(bv0.w),
                                        dup2(bv1.x), dup2(bv1.y), dup2(bv1.z), dup2(bv1.w)};
#pragma unroll
            for (int a = 0; a < 4; a++)
#pragma unroll
                for (int bj = 0; bj < 8; bj++) ffma2(acc[a][bj], ap[a], bd[bj]);
        }
        __syncthreads();
    }

    union UF { unsigned long long u; float2 f; };
#pragma unroll
    for (int a = 0; a < 4; a++) {
        int mrow = m0 + ((a & 2) ? 64 : 0) + ty * 4 + (a & 1) * 2;
        UF u0, u1, u2, u3;
        u0.u = acc[a][0]; u1.u = acc[a][1]; u2.u = acc[a][2]; u3.u = acc[a][3];
        float4 lo0 = make_float4(u0.f.x, u1.f.x, u2.f.x, u3.f.x);
        float4 hi0 = make_float4(u0.f.y, u1.f.y, u2.f.y, u3.f.y);
        u0.u = acc[a][4]; u1.u = acc[a][5]; u2.u = acc[a][6]; u3.u = acc[a][7];
        float4 lo1 = make_float4(u0.f.x, u1.f.x, u2.f.x, u3.f.x);
        float4 hi1 = make_float4(u0.f.y, u1.f.y, u2.f.y, u3.f.y);
        float* c0 = &Cm[(size_t)mrow * N + n0 + tx * 4];
        *(float4*)c0 = lo0;
        *(float4*)(c0 + 64) = lo1;
        float* c1 = &Cm[(size_t)(mrow + 1) * N + n0 + tx * 4];
        *(float4*)c1 = hi0;
        *(float4*)(c1 + 64) = hi1;
    }
}

// -------- diagonal-shift sum of Gram + normalization: yscore -> g_bufB -------
__global__ void k_diagsum() {
    int q = blockIdx.x * 256 + threadIdx.x;
    int r = blockIdx.y; int bb = blockIdx.z;
    int i = r >> 6, j = r & 63, pi = q >> 6, pj = q & 63;
    const float* G = g_bufA + (size_t)bb * LL * LL;
    float acc = 0.f;
#pragma unroll
    for (int du = -1; du <= 1; du++)
#pragma unroll
        for (int dv = -1; dv <= 1; dv++) {
            if ((unsigned)(i + du) < 64u && (unsigned)(j + dv) < 64u &&
                (unsigned)(pi + du) < 64u && (unsigned)(pj + dv) < 64u)
                acc += G[(size_t)(r + du * 64 + dv) * LL + (q + du * 64 + dv)];
        }
    g_bufB[(size_t)bb * LL * LL + (size_t)r * LL + q] = acc * g_inorm[bb * LL + r];
}

// -------- fuse conv #1 (flat diagonal 3-tap with wrap artifact): -> g_bufA ---
__global__ void k_fuse1() {
    int idx = blockIdx.x * 256 + threadIdx.x;            // LL*LL per batch
    int bb = blockIdx.y;
    int q = idx & 4095, r = idx >> 12;
    const float* Y = g_bufB + (size_t)bb * LL * LL;
    float acc = 0.f;
#pragma unroll
    for (int d = -1; d <= 1; d++) {
        int rr = r + d, qq = q + d;
        if ((unsigned)rr < (unsigned)LL && (unsigned)qq < (unsigned)LL)
            acc += Y[(size_t)rr * LL + qq];
    }
    g_bufA[(size_t)bb * LL * LL + idx] = acc;
}

// -------- fuse conv #2 on transposed view, output in final [l][p] layout -----
__global__ void k_fuse2() {
    int idx = blockIdx.x * 256 + threadIdx.x;
    int bb = blockIdx.y;
    int p = idx & 4095, l = idx >> 12;
    int hb = l >> 6, wb = l & 63, hf = p >> 6, wf = p & 63;
    int r2 = wb * 64 + hb, q2 = wf * 64 + hf;
    const float* Z = g_bufA + (size_t)bb * LL * LL;
    float acc = 0.f;
#pragma unroll
    for (int d = -1; d <= 1; d++) {
        int rr = r2 + d, qq = q2 + d;
        if ((unsigned)rr < (unsigned)LL && (unsigned)qq < (unsigned)LL)
            acc += Z[(size_t)(((rr & 63) << 6) + (rr >> 6)) * LL + (((qq & 63) << 6) + (qq >> 6))];
    }
    g_bufB[(size_t)bb * LL * LL + idx] = acc;
}

// -------- column softmax over l (with mask, SCALE=10) ------------------------
__global__ void k_colmax() {
    int p = blockIdx.x * 256 + threadIdx.x;
    int chunk = blockIdx.y, bb = blockIdx.z;
    const float* Y = g_bufB + (size_t)bb * LL * LL;
    float mx = -1e30f;
    for (int r = chunk * 256; r < chunk * 256 + 256; r++) {
        float v = Y[(size_t)r * LL + p] * (g_mm[r] * 10.f);
        mx = fmaxf(mx, v);
    }
    g_pmax[(bb * 16 + chunk) * LL + p] = mx;
}

__global__ void k_cmaxred() {
    int idx = blockIdx.x * 256 + threadIdx.x;            // NB*LL
    int bb = idx >> 12; int p = idx & 4095;
    float mx = -1e30f;
    for (int c = 0; c < 16; c++) mx = fmaxf(mx, g_pmax[(bb * 16 + c) * LL + p]);
    g_cmax[idx] = mx;
}

__global__ void k_exp() {
    int p = blockIdx.x * 256 + threadIdx.x;
    int chunk = blockIdx.y, bb = blockIdx.z;
    const float* Y = g_bufB + (size_t)bb * LL * LL;
    float* E = g_bufA + (size_t)bb * LL * LL;
    float mx = g_cmax[bb * LL + p];
    float s = 0.f;
    for (int r = chunk * 256; r < chunk * 256 + 256; r++) {
        float lm = g_mm[r];
        float v = Y[(size_t)r * LL + p] * (lm * 10.f);
        float e = __expf(v - mx);
        s += e;
        E[(size_t)r * LL + p] = e * lm;
    }
    g_psum[(bb * 16 + chunk) * LL + p] = s;
}

__global__ void k_rinv() {
    int idx = blockIdx.x * 256 + threadIdx.x;            // NB*LL
    int bb = idx >> 12; int p = idx & 4095;
    float s = 0.f;
    for (int c = 0; c < 16; c++) s += g_psum[(bb * 16 + c) * LL + p];
    g_rinv[idx] = 1.f / s;
}

// -------- pack raw 4x4 patches of b: W[b][l][c*16+kh*4+kw] -------------------
__global__ void k_packw(const float* __restrict__ b) {
    int idx = blockIdx.x * 256 + threadIdx.x;            // NB*LL*ND
    int n = idx & 2047, l = (idx >> 11) & 4095, bb = idx >> 23;
    int kw = n & 3, kh = (n >> 2) & 3, c = n >> 4;
    int li = l >> 6, lj = l & 63;
    int row = 2 * li - 1 + kh, col = 2 * lj - 1 + kw;
    float v = 0.f;
    if ((unsigned)row < 128u && (unsigned)col < 128u)
        v = b[((size_t)(bb * CC + c) * 128 + row) * 128 + col];
    g_wmat[idx] = v;
}

// -------- gather transposed-conv output, fold rinv and /4 --------------------
__global__ void k_gather(float* __restrict__ out) {
    int idx = blockIdx.x * 256 + threadIdx.x;            // NB*CC*128*128
    int ow = idx & 127, oh = (idx >> 7) & 127, c = (idx >> 14) & 127, bb = idx >> 21;
    const float* P = g_v + (size_t)bb * LL * ND;
    const float* rin = g_rinv + bb * LL;
    float acc = 0.f;
#pragma unroll
    for (int kh = 0; kh < 4; kh++) {
        int th = oh + 1 - kh;
        if (th & 1) continue;
        int ih = th >> 1;
        if ((unsigned)ih >= 64u) continue;
#pragma unroll
        for (int kw = 0; kw < 4; kw++) {
            int tw = ow + 1 - kw;
            if (tw & 1) continue;
            int iw = tw >> 1;
            if ((unsigned)iw >= 64u) continue;
            int p = ih * 64 + iw;
            acc += P[(size_t)p * ND + c * 16 + kh * 4 + kw] * rin[p];
        }
    }
    out[idx] = acc * 0.25f;
}

// ---------------- launch -----------------------------------------------------
extern "C" void kernel_launch(void* const* d_in, const int* in_sizes, int n_in,
                              void* d_out, int out_size) {
    const float* f = (const float*)d_in[0];
    const float* b = (const float*)d_in[1];
    const float* mask = (const float*)d_in[2];
    float* out = (float*)d_out;

    k_downsample<<<4096, 256>>>(f, b);
    k_stats<<<32, 256>>>();
    k_normmm<<<32, 256>>>(mask);

    // Gram: G[l][p] = sum_c bds[c][l]*fds[c][p]
    gemm_tn<<<dim3(32, 32, NB), 256>>>(0, LL, LL, CC,
                                       (size_t)CC * LL, (size_t)CC * LL, (size_t)LL * LL);
    k_diagsum<<<dim3(16, 4096, NB), 256>>>();
    k_fuse1<<<dim3(65536, NB), 256>>>();
    k_fuse2<<<dim3(65536, NB), 256>>>();
    k_colmax<<<dim3(16, 16, NB), 256>>>();
    k_cmaxred<<<32, 256>>>();
    k_exp<<<dim3(16, 16, NB), 256>>>();
    k_rinv<<<32, 256>>>();
    k_packw<<<dim3(65536), 256>>>(b);

    // P[p][n] = sum_l E[l][p] * W[l][n]
    gemm_tn<<<dim3(16, 32, NB), 256>>>(1, LL, ND, LL,
                                       (size_t)LL * LL, (size_t)LL * ND, (size_t)LL * ND);
    k_gather<<<16384, 256>>>(out);
}

// round 3
// speedup vs baseline: 1.3665x; 1.3665x over previous
#include <cuda_runtime.h>
#include <math.h>

#define CC 128
#define HS 64
#define LL 4096
#define ND 2048   // CC*16
#define NB 2
#define CAP 2048

// ---------------- device scratch (module-scope, no runtime alloc) -------------
__device__ float g_fds[NB * CC * LL];
__device__ float g_bds[NB * CC * LL];
__device__ float g_S[NB * LL];
__device__ float g_inorm[NB * LL];
__device__ float g_mm[LL];
__device__ float g_bufA[(size_t)NB * LL * LL];   // G -> logits
__device__ float g_bufB[(size_t)NB * LL * LL];   // yscore
__device__ float g_pmax[NB * 16 * LL];
__device__ float g_cmax[NB * LL];
__device__ float g_rinv[NB * LL];
__device__ float g_wmat[(size_t)NB * LL * ND];
__device__ float g_v[(size_t)NB * LL * ND];
__device__ int   g_cnt[NB * LL];
__device__ int   g_sidx[(size_t)NB * LL * CAP];
__device__ float g_sval[(size_t)NB * LL * CAP];

// ---------------- small kernels ----------------------------------------------
__global__ void k_downsample(const float* __restrict__ f, const float* __restrict__ b) {
    int idx = blockIdx.x * 256 + threadIdx.x;           // NB*CC*64*64
    int j = idx & 63, i = (idx >> 6) & 63;
    int c = (idx >> 12) & 127, bb = idx >> 19;
    size_t src = ((size_t)(bb * CC + c) * 128 + 2 * i) * 128 + 2 * j;
    g_fds[idx] = f[src];
    g_bds[idx] = b[src];
}

__global__ void k_stats() {                              // S[b][l] = sum_c bds^2
    int idx = blockIdx.x * 256 + threadIdx.x;            // NB*LL
    int bb = idx >> 12; int l = idx & 4095;
    float acc = 0.f;
    for (int c = 0; c < CC; c++) {
        float v = g_bds[((size_t)bb * CC + c) * LL + l];
        acc = fmaf(v, v, acc);
    }
    g_S[idx] = acc;
}

__global__ void k_normmm(const float* __restrict__ mask) {
    int idx = blockIdx.x * 256 + threadIdx.x;            // NB*LL
    int bb = idx >> 12; int l = idx & 4095;
    int i = l >> 6, j = l & 63;
    float acc = 0.1152f;                                 // 1152 * 1e-4
    float msum = 0.f;
    for (int du = -1; du <= 1; du++)
        for (int dv = -1; dv <= 1; dv++) {
            int ii = i + du, jj = j + dv;
            if (ii >= 0 && ii < 64 && jj >= 0 && jj < 64) {
                acc += g_S[bb * LL + ii * 64 + jj];
                if (bb == 0) msum += mask[(2 * ii) * 128 + 2 * jj];
            }
        }
    g_inorm[idx] = rsqrtf(acc);
    if (bb == 0) g_mm[l] = (msum == 0.f) ? 1.f : 0.f;
}

// ---------------- packed f32x2 SGEMM (Gram): G[l][p] = sum_c bds[c][l]*fds[c][p]
#define BM 128
#define BN 128
#define BKK 16

__device__ __forceinline__ unsigned long long dup2(float x) {
    unsigned long long r;
    asm("mov.b64 %0, {%1, %2};" : "=l"(r) : "f"(x), "f"(x));
    return r;
}
__device__ __forceinline__ void ffma2(unsigned long long& d, unsigned long long a, unsigned long long b) {
    asm("fma.rn.f32x2 %0, %1, %2, %0;" : "+l"(d) : "l"(a), "l"(b));
}

__global__ __launch_bounds__(256, 2)
void gemm_gram() {
    const int M = LL, N = LL, K = CC;
    const float* A = g_bds; const float* Bm = g_fds; float* Cm = g_bufA;
    __shared__ float As[BKK][BM];
    __shared__ float Bs[BKK][BN];
    const int tid = threadIdx.x;
    const int m0 = blockIdx.y * BM, n0 = blockIdx.x * BN;
    const int z = blockIdx.z;
    A += (size_t)z * CC * LL; Bm += (size_t)z * CC * LL; Cm += (size_t)z * LL * LL;

    int lk[2], lm4[2];
#pragma unroll
    for (int r = 0; r < 2; r++) {
        int idx = tid + r * 256;
        lk[r] = idx >> 5;
        lm4[r] = (idx & 31) << 2;
    }

    unsigned long long acc[4][8];
#pragma unroll
    for (int a = 0; a < 4; a++)
#pragma unroll
        for (int b = 0; b < 8; b++) acc[a][b] = 0ull;

    const int ty = tid >> 4, tx = tid & 15;

    for (int k0 = 0; k0 < K; k0 += BKK) {
#pragma unroll
        for (int r = 0; r < 2; r++) {
            *(float4*)&As[lk[r]][lm4[r]] = *(const float4*)&A[(size_t)(k0 + lk[r]) * M + m0 + lm4[r]];
            *(float4*)&Bs[lk[r]][lm4[r]] = *(const float4*)&Bm[(size_t)(k0 + lk[r]) * N + n0 + lm4[r]];
        }
        __syncthreads();
#pragma unroll
        for (int kk = 0; kk < BKK; kk++) {
            const ulonglong2* A2 = (const ulonglong2*)&As[kk][0];
            ulonglong2 av0 = A2[ty];
            ulonglong2 av1 = A2[16 + ty];
            unsigned long long ap[4] = {av0.x, av0.y, av1.x, av1.y};
            const float4* B4 = (const float4*)&Bs[kk][0];
            float4 bv0 = B4[tx], bv1 = B4[16 + tx];
            unsigned long long bd[8] = {dup2(bv0.x), dup2(bv0.y), dup2(bv0.z), dup2(bv0.w),
                                        dup2(bv1.x), dup2(bv1.y), dup2(bv1.z), dup2(bv1.w)};
#pragma unroll
            for (int a = 0; a < 4; a++)
#pragma unroll
                for (int bj = 0; bj < 8; bj++) ffma2(acc[a][bj], ap[a], bd[bj]);
        }
        __syncthreads();
    }

    union UF { unsigned long long u; float2 f; };
#pragma unroll
    for (int a = 0; a < 4; a++) {
        int mrow = m0 + ((a & 2) ? 64 : 0) + ty * 4 + (a & 1) * 2;
        UF u0, u1, u2, u3;
        u0.u = acc[a][0]; u1.u = acc[a][1]; u2.u = acc[a][2]; u3.u = acc[a][3];
        float4 lo0 = make_float4(u0.f.x, u1.f.x, u2.f.x, u3.f.x);
        float4 hi0 = make_float4(u0.f.y, u1.f.y, u2.f.y, u3.f.y);
        u0.u = acc[a][4]; u1.u = acc[a][5]; u2.u = acc[a][6]; u3.u = acc[a][7];
        float4 lo1 = make_float4(u0.f.x, u1.f.x, u2.f.x, u3.f.x);
        float4 hi1 = make_float4(u0.f.y, u1.f.y, u2.f.y, u3.f.y);
        float* c0 = &Cm[(size_t)mrow * N + n0 + tx * 4];
        *(float4*)c0 = lo0;
        *(float4*)(c0 + 64) = lo1;
        float* c1 = &Cm[(size_t)(mrow + 1) * N + n0 + tx * 4];
        *(float4*)c1 = hi0;
        *(float4*)(c1 + 64) = hi1;
    }
}

// -------- diagonal-shift sum of Gram + normalization: G(bufA) -> y(bufB) -----
__global__ void k_diagsum() {
    int q = blockIdx.x * 256 + threadIdx.x;
    int r = blockIdx.y; int bb = blockIdx.z;
    int i = r >> 6, j = r & 63, pi = q >> 6, pj = q & 63;
    const float* G = g_bufA + (size_t)bb * LL * LL;
    float acc = 0.f;
#pragma unroll
    for (int du = -1; du <= 1; du++)
#pragma unroll
        for (int dv = -1; dv <= 1; dv++) {
            if ((unsigned)(i + du) < 64u && (unsigned)(j + dv) < 64u &&
                (unsigned)(pi + du) < 64u && (unsigned)(pj + dv) < 64u)
                acc += G[(size_t)(r + du * 64 + dv) * LL + (q + du * 64 + dv)];
        }
    g_bufB[(size_t)bb * LL * LL + (size_t)r * LL + q] = acc * g_inorm[bb * LL + r];
}

// -------- fused fuse1+fuse2 (both flat 3-tap diagonals, incl. wrap artifacts),
//          writes LOGITS = yfused * mm[l] * 10 into bufA in final [l][p] layout
__device__ __forceinline__ int Tsw(int x) { return ((x & 63) << 6) | (x >> 6); }

__global__ void k_fuse12() {
    int p = blockIdx.x * 256 + threadIdx.x;
    int l = blockIdx.y; int bb = blockIdx.z;
    const float* Y = g_bufB + (size_t)bb * LL * LL;
    int r2 = Tsw(l), q2 = Tsw(p);
    float acc = 0.f;
#pragma unroll
    for (int d2 = -1; d2 <= 1; d2++) {
        int rr = r2 + d2, qq = q2 + d2;
        if ((unsigned)rr >= (unsigned)LL || (unsigned)qq >= (unsigned)LL) continue;
        int a2 = Tsw(rr), b2 = Tsw(qq);
#pragma unroll
        for (int d1 = -1; d1 <= 1; d1++) {
            int aa = a2 + d1, bbq = b2 + d1;
            if ((unsigned)aa < (unsigned)LL && (unsigned)bbq < (unsigned)LL)
                acc += Y[(size_t)aa * LL + bbq];
        }
    }
    g_bufA[(size_t)bb * LL * LL + (size_t)l * LL + p] = acc * (g_mm[l] * 10.f);
}

// -------- column max over l (logits already scaled+masked) -------------------
__global__ void k_colmax() {
    int p = blockIdx.x * 256 + threadIdx.x;
    int chunk = blockIdx.y, bb = blockIdx.z;
    const float* Lg = g_bufA + (size_t)bb * LL * LL;
    float mx = -1e30f;
    for (int r = chunk * 256; r < chunk * 256 + 256; r++)
        mx = fmaxf(mx, Lg[(size_t)r * LL + p]);
    g_pmax[(bb * 16 + chunk) * LL + p] = mx;
}

__global__ void k_cmaxred() {
    int idx = blockIdx.x * 256 + threadIdx.x;            // NB*LL
    int bb = idx >> 12; int p = idx & 4095;
    float mx = -1e30f;
    for (int c = 0; c < 16; c++) mx = fmaxf(mx, g_pmax[(bb * 16 + c) * LL + p]);
    g_cmax[idx] = mx;
}

// -------- threshold select + softmax sum: logits -> (idx, e) lists + rinv ----
__global__ void k_select() {
    int p = blockIdx.x * 256 + threadIdx.x;
    int bb = blockIdx.y;
    const float* Lg = g_bufA + (size_t)bb * LL * LL;
    float mx = g_cmax[bb * LL + p];
    float thr = mx - 25.f;                               // exp(-25)*4096 ~ 6e-8 rel
    float s = 0.f;
    int cnt = 0;
    int* idx = g_sidx + ((size_t)bb * LL + p) * CAP;
    float* val = g_sval + ((size_t)bb * LL + p) * CAP;
    for (int l = 0; l < LL; l++) {
        float v = Lg[(size_t)l * LL + p];
        if (v > thr) {
            float e = __expf(v - mx);
            s += e;
            if (g_mm[l] > 0.f && cnt < CAP) { idx[cnt] = l; val[cnt] = e; cnt++; }
        }
    }
    g_cnt[bb * LL + p] = cnt;
    g_rinv[bb * LL + p] = 1.f / s;
}

// -------- pack raw 4x4 patches of b: W[b][l][c*16+kh*4+kw] -------------------
__global__ void k_packw(const float* __restrict__ b) {
    int idx = blockIdx.x * 256 + threadIdx.x;            // NB*LL*ND
    int n = idx & 2047, l = (idx >> 11) & 4095, bb = idx >> 23;
    int kw = n & 3, kh = (n >> 2) & 3, c = n >> 4;
    int li = l >> 6, lj = l & 63;
    int row = 2 * li - 1 + kh, col = 2 * lj - 1 + kw;
    float v = 0.f;
    if ((unsigned)row < 128u && (unsigned)col < 128u)
        v = b[((size_t)(bb * CC + c) * 128 + row) * 128 + col];
    g_wmat[idx] = v;
}

// -------- sparse attn @ W: g_v[p][n] = sum_{selected l} e * W[l][n] ----------
__global__ __launch_bounds__(256, 4)
void k_spmm() {
    int p = blockIdx.x, bb = blockIdx.y;
    int tid = threadIdx.x;
    int cnt = g_cnt[bb * LL + p];
    const int* idx = g_sidx + ((size_t)bb * LL + p) * CAP;
    const float* val = g_sval + ((size_t)bb * LL + p) * CAP;
    const float* W = g_wmat + (size_t)bb * LL * ND;
    float4 a0 = make_float4(0.f, 0.f, 0.f, 0.f);
    float4 a1 = make_float4(0.f, 0.f, 0.f, 0.f);
    for (int i = 0; i < cnt; i++) {
        int l = idx[i];
        float e = val[i];
        const float4* w = (const float4*)(W + (size_t)l * ND);
        float4 w0 = w[tid], w1 = w[tid + 256];
        a0.x = fmaf(e, w0.x, a0.x); a0.y = fmaf(e, w0.y, a0.y);
        a0.z = fmaf(e, w0.z, a0.z); a0.w = fmaf(e, w0.w, a0.w);
        a1.x = fmaf(e, w1.x, a1.x); a1.y = fmaf(e, w1.y, a1.y);
        a1.z = fmaf(e, w1.z, a1.z); a1.w = fmaf(e, w1.w, a1.w);
    }
    float4* out = (float4*)(g_v + (size_t)(bb * LL + p) * ND);
    out[tid] = a0;
    out[tid + 256] = a1;
}

// -------- gather transposed-conv output, fold rinv and /4 --------------------
__global__ void k_gather(float* __restrict__ out) {
    int idx = blockIdx.x * 256 + threadIdx.x;            // NB*CC*128*128
    int ow = idx & 127, oh = (idx >> 7) & 127, c = (idx >> 14) & 127, bb = idx >> 21;
    const float* P = g_v + (size_t)bb * LL * ND;
    const float* rin = g_rinv + bb * LL;
    float acc = 0.f;
#pragma unroll
    for (int kh = 0; kh < 4; kh++) {
        int th = oh + 1 - kh;
        if (th & 1) continue;
        int ih = th >> 1;
        if ((unsigned)ih >= 64u) continue;
#pragma unroll
        for (int kw = 0; kw < 4; kw++) {
            int tw = ow + 1 - kw;
            if (tw & 1) continue;
            int iw = tw >> 1;
            if ((unsigned)iw >= 64u) continue;
            int p = ih * 64 + iw;
            acc += P[(size_t)p * ND + c * 16 + kh * 4 + kw] * rin[p];
        }
    }
    out[idx] = acc * 0.25f;
}

// ---------------- launch -----------------------------------------------------
extern "C" void kernel_launch(void* const* d_in, const int* in_sizes, int n_in,
                              void* d_out, int out_size) {
    const float* f = (const float*)d_in[0];
    const float* b = (const float*)d_in[1];
    const float* mask = (const float*)d_in[2];
    float* out = (float*)d_out;

    k_downsample<<<4096, 256>>>(f, b);
    k_stats<<<32, 256>>>();
    k_normmm<<<32, 256>>>(mask);
    gemm_gram<<<dim3(32, 32, NB), 256>>>();
    k_diagsum<<<dim3(16, 4096, NB), 256>>>();
    k_fuse12<<<dim3(16, 4096, NB), 256>>>();
    k_colmax<<<dim3(16, 16, NB), 256>>>();
    k_cmaxred<<<32, 256>>>();
    k_select<<<dim3(16, NB), 256>>>();
    k_packw<<<65536, 256>>>(b);
    k_spmm<<<dim3(4096, NB), 256>>>();
    k_gather<<<16384, 256>>>(out);
}

// round 4
// speedup vs baseline: 4.1390x; 3.0290x over previous
#include <cuda_runtime.h>
#include <math.h>

#define CC 128
#define HS 64
#define LL 4096
#define ND 2048   // CC*16
#define NB 2
#define LCH 16        // l-chunk per stencil block
#define NCH (LL/LCH)  // 256 chunks for pmax
#define SCH 16        // select chunks
#define CAPC 256      // per-chunk list capacity (cannot overflow: 256 l per chunk)

// ---------------- device scratch (module-scope, no runtime alloc) -------------
__device__ float g_fds[NB * CC * LL];
__device__ float g_bds[NB * CC * LL];
__device__ float g_S[NB * LL];
__device__ float g_inorm[NB * LL];
__device__ float g_mm[LL];
__device__ float g_bufA[(size_t)NB * LL * LL];   // G -> logits
__device__ float g_bufB[(size_t)NB * LL * LL];   // yscore
__device__ float g_pmax[NB * NCH * LL];
__device__ float g_cmax[NB * LL];
__device__ float g_rinv[NB * LL];
__device__ float g_wmat[(size_t)NB * LL * ND];
__device__ float g_v[(size_t)NB * LL * ND];
__device__ int   g_cntc[NB * LL * SCH];
__device__ float g_psumc[NB * LL * SCH];
__device__ int   g_sidx[(size_t)NB * LL * SCH * CAPC];
__device__ float g_sval[(size_t)NB * LL * SCH * CAPC];

// ---------------- small kernels ----------------------------------------------
__global__ void k_downsample(const float* __restrict__ f, const float* __restrict__ b) {
    int idx = blockIdx.x * 256 + threadIdx.x;           // NB*CC*64*64
    int j = idx & 63, i = (idx >> 6) & 63;
    int c = (idx >> 12) & 127, bb = idx >> 19;
    size_t src = ((size_t)(bb * CC + c) * 128 + 2 * i) * 128 + 2 * j;
    g_fds[idx] = f[src];
    g_bds[idx] = b[src];
}

__global__ void k_stats() {                              // S[b][l] = sum_c bds^2
    int idx = blockIdx.x * 256 + threadIdx.x;            // NB*LL
    int bb = idx >> 12; int l = idx & 4095;
    float acc = 0.f;
    for (int c = 0; c < CC; c++) {
        float v = g_bds[((size_t)bb * CC + c) * LL + l];
        acc = fmaf(v, v, acc);
    }
    g_S[idx] = acc;
}

__global__ void k_normmm(const float* __restrict__ mask) {
    int idx = blockIdx.x * 256 + threadIdx.x;            // NB*LL
    int bb = idx >> 12; int l = idx & 4095;
    int i = l >> 6, j = l & 63;
    float acc = 0.1152f;                                 // 1152 * 1e-4
    float msum = 0.f;
    for (int du = -1; du <= 1; du++)
        for (int dv = -1; dv <= 1; dv++) {
            int ii = i + du, jj = j + dv;
            if (ii >= 0 && ii < 64 && jj >= 0 && jj < 64) {
                acc += g_S[bb * LL + ii * 64 + jj];
                if (bb == 0) msum += mask[(2 * ii) * 128 + 2 * jj];
            }
        }
    g_inorm[idx] = rsqrtf(acc);
    if (bb == 0) g_mm[l] = (msum == 0.f) ? 1.f : 0.f;
}

// ---------------- packed f32x2 SGEMM (Gram): G[l][p] = sum_c bds[c][l]*fds[c][p]
#define BM 128
#define BN 128
#define BKK 16

__device__ __forceinline__ unsigned long long dup2(float x) {
    unsigned long long r;
    asm("mov.b64 %0, {%1, %2};" : "=l"(r) : "f"(x), "f"(x));
    return r;
}
__device__ __forceinline__ void ffma2(unsigned long long& d, unsigned long long a, unsigned long long b) {
    asm("fma.rn.f32x2 %0, %1, %2, %0;" : "+l"(d) : "l"(a), "l"(b));
}

__global__ __launch_bounds__(256, 2)
void gemm_gram() {
    const int M = LL, N = LL, K = CC;
    const float* A = g_bds; const float* Bm = g_fds; float* Cm = g_bufA;
    __shared__ float As[BKK][BM];
    __shared__ float Bs[BKK][BN];
    const int tid = threadIdx.x;
    const int m0 = blockIdx.y * BM, n0 = blockIdx.x * BN;
    const int z = blockIdx.z;
    A += (size_t)z * CC * LL; Bm += (size_t)z * CC * LL; Cm += (size_t)z * LL * LL;

    int lk[2], lm4[2];
#pragma unroll
    for (int r = 0; r < 2; r++) {
        int idx = tid + r * 256;
        lk[r] = idx >> 5;
        lm4[r] = (idx & 31) << 2;
    }

    unsigned long long acc[4][8];
#pragma unroll
    for (int a = 0; a < 4; a++)
#pragma unroll
        for (int b = 0; b < 8; b++) acc[a][b] = 0ull;

    const int ty = tid >> 4, tx = tid & 15;

    for (int k0 = 0; k0 < K; k0 += BKK) {
#pragma unroll
        for (int r = 0; r < 2; r++) {
            *(float4*)&As[lk[r]][lm4[r]] = *(const float4*)&A[(size_t)(k0 + lk[r]) * M + m0 + lm4[r]];
            *(float4*)&Bs[lk[r]][lm4[r]] = *(const float4*)&Bm[(size_t)(k0 + lk[r]) * N + n0 + lm4[r]];
        }
        __syncthreads();
#pragma unroll
        for (int kk = 0; kk < BKK; kk++) {
            const ulonglong2* A2 = (const ulonglong2*)&As[kk][0];
            ulonglong2 av0 = A2[ty];
            ulonglong2 av1 = A2[16 + ty];
            unsigned long long ap[4] = {av0.x, av0.y, av1.x, av1.y};
            const float4* B4 = (const float4*)&Bs[kk][0];
            float4 bv0 = B4[tx], bv1 = B4[16 + tx];
            unsigned long long bd[8] = {dup2(bv0.x), dup2(bv0.y), dup2(bv0.z), dup2(bv0.w),
                                        dup2(bv1.x), dup2(bv1.y), dup2(bv1.z), dup2(bv1.w)};
#pragma unroll
            for (int a = 0; a < 4; a++)
#pragma unroll
                for (int bj = 0; bj < 8; bj++) ffma2(acc[a][bj], ap[a], bd[bj]);
        }
        __syncthreads();
    }

    union UF { unsigned long long u; float2 f; };
#pragma unroll
    for (int a = 0; a < 4; a++) {
        int mrow = m0 + ((a & 2) ? 64 : 0) + ty * 4 + (a & 1) * 2;
        UF u0, u1, u2, u3;
        u0.u = acc[a][0]; u1.u = acc[a][1]; u2.u = acc[a][2]; u3.u = acc[a][3];
        float4 lo0 = make_float4(u0.f.x, u1.f.x, u2.f.x, u3.f.x);
        float4 hi0 = make_float4(u0.f.y, u1.f.y, u2.f.y, u3.f.y);
        u0.u = acc[a][4]; u1.u = acc[a][5]; u2.u = acc[a][6]; u3.u = acc[a][7];
        float4 lo1 = make_float4(u0.f.x, u1.f.x, u2.f.x, u3.f.x);
        float4 hi1 = make_float4(u0.f.y, u1.f.y, u2.f.y, u3.f.y);
        float* c0 = &Cm[(size_t)mrow * N + n0 + tx * 4];
        *(float4*)c0 = lo0;
        *(float4*)(c0 + 64) = lo1;
        float* c1 = &Cm[(size_t)(mrow + 1) * N + n0 + tx * 4];
        *(float4*)c1 = hi0;
        *(float4*)(c1 + 64) = hi1;
    }
}

// -------- diagonal-shift sum of Gram + normalization: G(bufA) -> y(bufB) -----
// chunked over r so consecutive blocks (x = r-chunk) reuse rows in L1/L2.
__global__ void k_diagsum() {
    int q = blockIdx.y * 256 + threadIdx.x;
    int r0 = blockIdx.x * LCH;
    int bb = blockIdx.z;
    int pi = q >> 6, pj = q & 63;
    const float* G = g_bufA + (size_t)bb * LL * LL;
    float* Y = g_bufB + (size_t)bb * LL * LL;
    // precompute column validity/offsets per tap (independent of r)
    bool qok[3][3]; int qoff[3][3];
#pragma unroll
    for (int du = -1; du <= 1; du++)
#pragma unroll
        for (int dv = -1; dv <= 1; dv++) {
            qok[du + 1][dv + 1] = ((unsigned)(pi + du) < 64u && (unsigned)(pj + dv) < 64u);
            qoff[du + 1][dv + 1] = q + du * 64 + dv;
        }
    for (int rr = 0; rr < LCH; rr++) {
        int r = r0 + rr;
        int i = r >> 6, j = r & 63;
        float acc = 0.f;
#pragma unroll
        for (int du = -1; du <= 1; du++)
#pragma unroll
            for (int dv = -1; dv <= 1; dv++) {
                if (qok[du + 1][dv + 1] &&
                    (unsigned)(i + du) < 64u && (unsigned)(j + dv) < 64u)
                    acc += G[(size_t)(r + du * 64 + dv) * LL + qoff[du + 1][dv + 1]];
            }
        Y[(size_t)r * LL + q] = acc * g_inorm[bb * LL + r];
    }
}

// -------- fused fuse1+fuse2 stencil -> logits (+ per-chunk column max) -------
__device__ __forceinline__ int Tsw(int x) { return ((x & 63) << 6) | (x >> 6); }

__global__ void k_logits() {
    int p = blockIdx.y * 256 + threadIdx.x;
    int l0 = blockIdx.x * LCH;
    int bb = blockIdx.z;
    const float* Y = g_bufB + (size_t)bb * LL * LL;
    float* Lg = g_bufA + (size_t)bb * LL * LL;
    // per-thread column bases per d2 (independent of l)
    int q2 = Tsw(p);
    bool cok[3]; int cbase[3];
#pragma unroll
    for (int d2 = -1; d2 <= 1; d2++) {
        int qq = q2 + d2;
        cok[d2 + 1] = ((unsigned)qq < (unsigned)LL);
        cbase[d2 + 1] = cok[d2 + 1] ? Tsw(qq) : 0;
    }
    float mx = -1e30f;
    for (int ll = 0; ll < LCH; ll++) {
        int l = l0 + ll;
        int r2 = Tsw(l);
        float acc = 0.f;
#pragma unroll
        for (int d2 = -1; d2 <= 1; d2++) {
            int rr = r2 + d2;
            if (!cok[d2 + 1] || (unsigned)rr >= (unsigned)LL) continue;
            int a2 = Tsw(rr);
            int b2 = cbase[d2 + 1];
#pragma unroll
            for (int d1 = -1; d1 <= 1; d1++) {
                int aa = a2 + d1, bq = b2 + d1;
                if ((unsigned)aa < (unsigned)LL && (unsigned)bq < (unsigned)LL)
                    acc += Y[(size_t)aa * LL + bq];
            }
        }
        float lg = acc * (g_mm[l] * 10.f);
        Lg[(size_t)l * LL + p] = lg;
        mx = fmaxf(mx, lg);
    }
    g_pmax[((size_t)bb * NCH + blockIdx.x) * LL + p] = mx;
}

__global__ void k_cmaxred() {
    int idx = blockIdx.x * 256 + threadIdx.x;            // NB*LL
    int bb = idx >> 12; int p = idx & 4095;
    float mx = -1e30f;
    for (int c = 0; c < NCH; c++) mx = fmaxf(mx, g_pmax[((size_t)bb * NCH + c) * LL + p]);
    g_cmax[idx] = mx;
}

// -------- chunked threshold select + partial softmax sums --------------------
__global__ void k_select() {
    int p = blockIdx.x * 256 + threadIdx.x;
    int lc = blockIdx.y;                                  // 0..SCH-1
    int bb = blockIdx.z;
    const float* Lg = g_bufA + (size_t)bb * LL * LL;
    float mx = g_cmax[bb * LL + p];
    float thr = mx - 25.f;                                // exp(-25)*4096 ~ 6e-8 rel
    float s = 0.f;
    int cnt = 0;
    size_t base = ((size_t)(bb * LL + p) * SCH + lc) * CAPC;
    int* idx = g_sidx + base;
    float* val = g_sval + base;
    int lend = lc * (LL / SCH) + (LL / SCH);
    for (int l = lc * (LL / SCH); l < lend; l++) {
        float v = Lg[(size_t)l * LL + p];
        if (v > thr) {
            float e = __expf(v - mx);
            s += e;
            if (g_mm[l] > 0.f) { idx[cnt] = l; val[cnt] = e; cnt++; }
        }
    }
    g_cntc[(bb * LL + p) * SCH + lc] = cnt;
    g_psumc[(bb * LL + p) * SCH + lc] = s;
}

__global__ void k_rinv() {
    int idx = blockIdx.x * 256 + threadIdx.x;            // NB*LL
    float s = 0.f;
    for (int c = 0; c < SCH; c++) s += g_psumc[idx * SCH + c];
    g_rinv[idx] = 1.f / s;
}

// -------- pack raw 4x4 patches of b: W[b][l][c*16+kh*4+kw] -------------------
__global__ void k_packw(const float* __restrict__ b) {
    int idx = blockIdx.x * 256 + threadIdx.x;            // NB*LL*ND
    int n = idx & 2047, l = (idx >> 11) & 4095, bb = idx >> 23;
    int kw = n & 3, kh = (n >> 2) & 3, c = n >> 4;
    int li = l >> 6, lj = l & 63;
    int row = 2 * li - 1 + kh, col = 2 * lj - 1 + kw;
    float v = 0.f;
    if ((unsigned)row < 128u && (unsigned)col < 128u)
        v = b[((size_t)(bb * CC + c) * 128 + row) * 128 + col];
    g_wmat[idx] = v;
}

// -------- sparse attn @ W: g_v[p][n] = sum_{selected l} e * W[l][n] ----------
__global__ __launch_bounds__(256, 4)
void k_spmm() {
    int p = blockIdx.x, bb = blockIdx.y;
    int tid = threadIdx.x;
    const float* W = g_wmat + (size_t)bb * LL * ND;
    float4 a0 = make_float4(0.f, 0.f, 0.f, 0.f);
    float4 a1 = make_float4(0.f, 0.f, 0.f, 0.f);
    for (int lc = 0; lc < SCH; lc++) {
        int cnt = g_cntc[(bb * LL + p) * SCH + lc];
        size_t base = ((size_t)(bb * LL + p) * SCH + lc) * CAPC;
        const int* idx = g_sidx + base;
        const float* val = g_sval + base;
        for (int i = 0; i < cnt; i++) {
            int l = idx[i];
            float e = val[i];
            const float4* w = (const float4*)(W + (size_t)l * ND);
            float4 w0 = w[tid], w1 = w[tid + 256];
            a0.x = fmaf(e, w0.x, a0.x); a0.y = fmaf(e, w0.y, a0.y);
            a0.z = fmaf(e, w0.z, a0.z); a0.w = fmaf(e, w0.w, a0.w);
            a1.x = fmaf(e, w1.x, a1.x); a1.y = fmaf(e, w1.y, a1.y);
            a1.z = fmaf(e, w1.z, a1.z); a1.w = fmaf(e, w1.w, a1.w);
        }
    }
    float4* out = (float4*)(g_v + (size_t)(bb * LL + p) * ND);
    out[tid] = a0;
    out[tid + 256] = a1;
}

// -------- gather transposed-conv output, fold rinv and /4 --------------------
__global__ void k_gather(float* __restrict__ out) {
    int idx = blockIdx.x * 256 + threadIdx.x;            // NB*CC*128*128
    int ow = idx & 127, oh = (idx >> 7) & 127, c = (idx >> 14) & 127, bb = idx >> 21;
    const float* P = g_v + (size_t)bb * LL * ND;
    const float* rin = g_rinv + bb * LL;
    float acc = 0.f;
#pragma unroll
    for (int kh = 0; kh < 4; kh++) {
        int th = oh + 1 - kh;
        if (th & 1) continue;
        int ih = th >> 1;
        if ((unsigned)ih >= 64u) continue;
#pragma unroll
        for (int kw = 0; kw < 4; kw++) {
            int tw = ow + 1 - kw;
            if (tw & 1) continue;
            int iw = tw >> 1;
            if ((unsigned)iw >= 64u) continue;
            int p = ih * 64 + iw;
            acc += P[(size_t)p * ND + c * 16 + kh * 4 + kw] * rin[p];
        }
    }
    out[idx] = acc * 0.25f;
}

// ---------------- launch -----------------------------------------------------
extern "C" void kernel_launch(void* const* d_in, const int* in_sizes, int n_in,
                              void* d_out, int out_size) {
    const float* f = (const float*)d_in[0];
    const float* b = (const float*)d_in[1];
    const float* mask = (const float*)d_in[2];
    float* out = (float*)d_out;

    k_downsample<<<4096, 256>>>(f, b);
    k_stats<<<32, 256>>>();
    k_normmm<<<32, 256>>>(mask);
    gemm_gram<<<dim3(32, 32, NB), 256>>>();
    k_diagsum<<<dim3(NCH, 16, NB), 256>>>();
    k_logits<<<dim3(NCH, 16, NB), 256>>>();
    k_cmaxred<<<32, 256>>>();
    k_select<<<dim3(16, SCH, NB), 256>>>();
    k_rinv<<<32, 256>>>();
    k_packw<<<65536, 256>>>(b);
    k_spmm<<<dim3(4096, NB), 256>>>();
    k_gather<<<16384, 256>>>(out);
}